// round 6
// baseline (speedup 1.0000x reference)
#include <cuda_runtime.h>
#include <cstdint>
#include <float.h>

#define BB 16
#define NN 2048
#define CC 80
#define NBK 2048          // key buckets (mantissa bits [22:12])

// ---------------- scratch (device globals; no allocations) ----------------
__device__ float4             g_xyxy [BB * NN];
__device__ float              g_obj  [BB * NN];
__device__ float              g_conf [BB * NN];
__device__ int                g_cls  [BB * NN];
__device__ unsigned long long g_key64[BB * NN];

__device__ float4             g_xyxy_s[BB * NN];
__device__ float              g_obj_s [BB * NN];
__device__ float              g_conf_s[BB * NN];
__device__ unsigned char      g_cls_s [BB * NN];
__device__ int                g_M[BB];

// ---------------- kernel 1: prep, FOUR threads per element ----------------
__global__ __launch_bounds__(128) void prep_kernel(const float* __restrict__ boxes,
                                                   const float* __restrict__ objn,
                                                   const float* __restrict__ logits,
                                                   float* __restrict__ out)
{
    int gid  = blockIdx.x * blockDim.x + threadIdx.x;
    int gw   = gid >> 2;            // element index
    int sub  = gid & 3;             // 0..3 within element group
    if (gw >= BB * NN) return;

    // each sub-thread scans 20 logits (5 float4), base class = sub*20
    const float4* lg4 = (const float4*)(logits + (size_t)gw * CC) + sub * 5;
    float v = -FLT_MAX;
    int   vi = 0;
    #pragma unroll
    for (int q = 0; q < 5; q++) {
        float4 x = lg4[q];
        int k = sub * 20 + q * 4;
        if (x.x > v) { v = x.x; vi = k;     }
        if (x.y > v) { v = x.y; vi = k + 1; }
        if (x.z > v) { v = x.z; vi = k + 2; }
        if (x.w > v) { v = x.w; vi = k + 3; }
    }
    // reduce across the 4-lane group (xor 1, xor 2), tie -> lowest index
    #pragma unroll
    for (int o = 1; o <= 2; o <<= 1) {
        float v2 = __shfl_xor_sync(0xFFFFFFFFu, v, o);
        int   i2 = __shfl_xor_sync(0xFFFFFFFFu, vi, o);
        if (v2 > v || (v2 == v && i2 < vi)) { v = v2; vi = i2; }
    }

    if (sub == 0) {
        float ob = objn[gw];
        float4 bx = ((const float4*)boxes)[gw];
        float4 xy;
        xy.x = bx.x - bx.z * 0.5f;
        xy.y = bx.y - bx.w * 0.5f;
        xy.z = bx.x + bx.z * 0.5f;
        xy.w = bx.y + bx.w * 0.5f;
        bool valid = ob > 0.5f;

        unsigned u = __float_as_uint(valid ? ob : -1.0f);
        u = (u & 0x80000000u) ? ~u : (u | 0x80000000u);
        unsigned idx = (unsigned)(gw & (NN - 1));
        g_key64[gw] = ((unsigned long long)u << 32) | (0xFFFFFFFFu - idx);

        g_xyxy[gw] = xy;
        g_obj [gw] = ob;
        g_conf[gw] = v;
        g_cls [gw] = vi;

        int b = gw / NN;
        float4* row = (float4*)(out + (size_t)gw * 8);
        row[0] = make_float4((float)b, 0.f, 0.f, 0.f);
        row[1] = make_float4(0.f, 0.f, 0.f, 0.f);
    }
}

// ---------------- kernel 2: per-batch counting sort of valid elements ----
// valid obj in (0.5, 1) -> exponent 126 -> bucket = mantissa[22:12], monotone.
__global__ __launch_bounds__(1024) void rank_kernel()
{
    __shared__ int                hist[NBK];   // counts, then scatter cursors
    __shared__ int                offs[NBK];   // descending-order start offsets
    __shared__ unsigned long long skey[NN];    // scattered keys (sorted at end)
    __shared__ int                wsum[32];
    __shared__ int                Msh;

    int b = blockIdx.x;
    int t = threadIdx.x;
    int lane = t & 31, warp = t >> 5;

    hist[t] = 0; hist[t + 1024] = 0;
    __syncthreads();

    unsigned long long k0 = g_key64[b * NN + t];
    unsigned long long k1 = g_key64[b * NN + t + 1024];
    bool v0 = (unsigned)(k0 >> 32) > 0x80000000u;
    bool v1 = (unsigned)(k1 >> 32) > 0x80000000u;
    int bk0 = (int)((k0 >> 44) & (NBK - 1));
    int bk1 = (int)((k1 >> 44) & (NBK - 1));
    if (v0) atomicAdd(&hist[bk0], 1);
    if (v1) atomicAdd(&hist[bk1], 1);
    __syncthreads();

    // exclusive scan over DESCENDING bucket order (largest key first)
    int c0 = hist[NBK - 1 - 2 * t];
    int c1 = hist[NBK - 2 - 2 * t];
    int sum = c0 + c1;
    int inc = sum;
    #pragma unroll
    for (int o = 1; o < 32; o <<= 1) {
        int a = __shfl_up_sync(0xFFFFFFFFu, inc, o);
        if (lane >= o) inc += a;
    }
    if (lane == 31) wsum[warp] = inc;
    __syncthreads();
    if (warp == 0) {
        int wv = wsum[lane];
        int winc = wv;
        #pragma unroll
        for (int o = 1; o < 32; o <<= 1) {
            int a = __shfl_up_sync(0xFFFFFFFFu, winc, o);
            if (lane >= o) winc += a;
        }
        wsum[lane] = winc - wv;   // exclusive warp offsets
    }
    __syncthreads();
    int excl = wsum[warp] + (inc - sum);
    offs[NBK - 1 - 2 * t] = excl;
    offs[NBK - 2 - 2 * t] = excl + c0;
    if (t == 1023) Msh = excl + sum;   // total valid count
    __syncthreads();

    // cursors = offs, then scatter keys into bucket slots
    hist[t] = offs[t];
    hist[t + 1024] = offs[t + 1024];
    __syncthreads();
    if (v0) { int s = atomicAdd(&hist[bk0], 1); skey[s] = k0; }
    if (v1) { int s = atomicAdd(&hist[bk1], 1); skey[s] = k1; }
    __syncthreads();

    // per-bucket insertion sort, descending u64 (stability via idx in low bits)
    #pragma unroll
    for (int rr = 0; rr < 2; rr++) {
        int bk = t + rr * 1024;
        int s = offs[bk], e = hist[bk];
        for (int i = s + 1; i < e; i++) {
            unsigned long long key = skey[i];
            int j = i - 1;
            while (j >= s && skey[j] < key) { skey[j + 1] = skey[j]; j--; }
            skey[j + 1] = key;
        }
    }
    __syncthreads();

    // gather sorted attributes to global
    int M = Msh;
    #pragma unroll
    for (int rr = 0; rr < 2; rr++) {
        int p = t + rr * 1024;
        if (p < M) {
            unsigned n = 0xFFFFFFFFu - (unsigned)(skey[p] & 0xFFFFFFFFu);
            int g = b * NN + (int)n;
            int d = b * NN + p;
            g_xyxy_s[d] = g_xyxy[g];
            g_obj_s [d] = g_obj [g];
            g_conf_s[d] = g_conf[g];
            g_cls_s [d] = (unsigned char)g_cls[g];
        }
    }
    if (t == 0) g_M[b] = M;
}

// ---------------- kernel 3: per-(batch,class) greedy NMS + output --------
#define NMS_WARPS 4
#define LCAP 128
__global__ __launch_bounds__(NMS_WARPS * 32) void nms_kernel(float* __restrict__ out)
{
    __shared__ unsigned short list_s [NMS_WARPS][LCAP];
    __shared__ unsigned char  alive_s[NMS_WARPS][LCAP];

    int warp = threadIdx.x >> 5;
    int lane = threadIdx.x & 31;
    int w = blockIdx.x * NMS_WARPS + warp;
    if (w >= BB * CC) return;
    int b = w / CC;
    int c = w % CC;

    int M = g_M[b];
    const unsigned char* cls = g_cls_s + b * NN;
    unsigned short* list  = list_s [warp];
    unsigned char*  alive = alive_s[warp];

    // ordered ballot-compaction of class members within the valid prefix
    int K = 0;
    for (int base = 0; base < M; base += 32) {
        int p = base + lane;
        bool match = (p < M) && (cls[p] == (unsigned char)c);
        unsigned mask = __ballot_sync(0xFFFFFFFFu, match);
        if (match) {
            int d = K + __popc(mask & ((1u << lane) - 1u));
            if (d < LCAP) list[d] = (unsigned short)p;
        }
        K += __popc(mask);
    }
    if (K > LCAP) K = LCAP;
    for (int k2 = lane; k2 < K; k2 += 32) alive[k2] = 1;
    __syncwarp();

    const float4* boxes = g_xyxy_s + b * NN;

    for (int i = 0; i < K - 1; i++) {
        if (alive[i]) {
            float4 bi = boxes[list[i]];
            float areaI = (bi.z - bi.x + 1.0f) * (bi.w - bi.y + 1.0f);
            for (int j = i + 1 + lane; j < K; j += 32) {
                if (alive[j]) {
                    float4 bj = boxes[list[j]];
                    float x1 = fmaxf(bi.x, bj.x);
                    float y1 = fmaxf(bi.y, bj.y);
                    float x2 = fminf(bi.z, bj.z);
                    float y2 = fminf(bi.w, bj.w);
                    float iw = fmaxf(x2 - x1 + 1.0f, 0.0f);
                    float ih = fmaxf(y2 - y1 + 1.0f, 0.0f);
                    float inter = iw * ih;
                    float areaJ = (bj.z - bj.x + 1.0f) * (bj.w - bj.y + 1.0f);
                    float iou = inter / (areaI + areaJ - inter);
                    if (iou >= 0.5f) alive[j] = 0;
                }
            }
        }
        __syncwarp();
    }

    for (int k2 = lane; k2 < K; k2 += 32) {
        if (alive[k2]) {
            int p = list[k2];
            float4 bx = boxes[p];
            float4* row = (float4*)(out + ((size_t)(b * NN + p)) * 8);
            row[0] = make_float4((float)b, bx.x, bx.y, bx.z);
            row[1] = make_float4(bx.w, g_obj_s[b * NN + p],
                                 g_conf_s[b * NN + p], (float)c);
        }
    }
}

// ---------------- launch ---------------------------------------------------
extern "C" void kernel_launch(void* const* d_in, const int* in_sizes, int n_in,
                              void* d_out, int out_size)
{
    const float* boxes  = nullptr;
    const float* objn   = nullptr;
    const float* logits = nullptr;
    for (int i = 0; i < n_in; i++) {
        if      (in_sizes[i] == BB * NN * 4)  boxes  = (const float*)d_in[i];
        else if (in_sizes[i] == BB * NN)      objn   = (const float*)d_in[i];
        else if (in_sizes[i] == BB * NN * CC) logits = (const float*)d_in[i];
    }
    float* out = (float*)d_out;

    prep_kernel<<<(BB * NN * 4 + 127) / 128, 128>>>(boxes, objn, logits, out);
    rank_kernel<<<BB, 1024>>>();
    nms_kernel<<<(BB * CC + NMS_WARPS - 1) / NMS_WARPS, NMS_WARPS * 32>>>(out);
}

// round 7
// speedup vs baseline: 1.4472x; 1.4472x over previous
#include <cuda_runtime.h>
#include <cstdint>
#include <float.h>

#define BB 16
#define NN 2048
#define CC 80
#define NBK 2048          // key buckets (mantissa bits [22:12])

// ---------------- scratch (device globals; no allocations) ----------------
__device__ float4             g_xyxy [BB * NN];
__device__ float              g_obj  [BB * NN];
__device__ float              g_conf [BB * NN];
__device__ int                g_cls  [BB * NN];
__device__ unsigned long long g_key64[BB * NN];

__device__ float4             g_xyxy_s[BB * NN];
__device__ float              g_obj_s [BB * NN];
__device__ float              g_conf_s[BB * NN];
__device__ unsigned char      g_cls_s [BB * NN];
__device__ int                g_M[BB];

// ---------------- kernel 1: prep, thread-per-element, valid-gated ---------
__global__ __launch_bounds__(128) void prep_kernel(const float* __restrict__ boxes,
                                                   const float* __restrict__ objn,
                                                   const float* __restrict__ logits,
                                                   float* __restrict__ out)
{
    int gw = blockIdx.x * blockDim.x + threadIdx.x;
    if (gw >= BB * NN) return;

    float ob = objn[gw];
    bool valid = ob > 0.5f;

    // sort key always (invalid -> key -1.0 sorts to the back)
    unsigned u = __float_as_uint(valid ? ob : -1.0f);
    u = (u & 0x80000000u) ? ~u : (u | 0x80000000u);
    unsigned idx = (unsigned)(gw & (NN - 1));
    g_key64[gw] = ((unsigned long long)u << 32) | (0xFFFFFFFFu - idx);

    // output row init always (batch index + zeros)
    int b = gw >> 11;
    float4* row = (float4*)(out + (size_t)gw * 8);
    row[0] = make_float4((float)b, 0.f, 0.f, 0.f);
    row[1] = make_float4(0.f, 0.f, 0.f, 0.f);

    // everything else only for VALID elements (downstream reads only prefix)
    if (!valid) return;

    const float4* lg4 = (const float4*)(logits + (size_t)gw * CC);
    float v = -FLT_MAX;
    int   vi = 0;
    #pragma unroll
    for (int q = 0; q < CC / 4; q++) {
        float4 x = lg4[q];
        int k = q * 4;
        if (x.x > v) { v = x.x; vi = k;     }
        if (x.y > v) { v = x.y; vi = k + 1; }
        if (x.z > v) { v = x.z; vi = k + 2; }
        if (x.w > v) { v = x.w; vi = k + 3; }
    }

    float4 bx = ((const float4*)boxes)[gw];
    float4 xy;
    xy.x = bx.x - bx.z * 0.5f;
    xy.y = bx.y - bx.w * 0.5f;
    xy.z = bx.x + bx.z * 0.5f;
    xy.w = bx.y + bx.w * 0.5f;

    g_xyxy[gw] = xy;
    g_obj [gw] = ob;
    g_conf[gw] = v;
    g_cls [gw] = vi;
}

// ---------------- kernel 2: per-batch counting sort of valid elements ----
// valid obj in (0.5, 1) -> exponent 126 -> bucket = mantissa[22:12], monotone.
__global__ __launch_bounds__(1024) void rank_kernel()
{
    __shared__ int                hist[NBK];   // counts, then scatter cursors
    __shared__ int                offs[NBK];   // descending-order start offsets
    __shared__ unsigned long long skey[NN];    // scattered keys (sorted at end)
    __shared__ int                wsum[32];
    __shared__ int                Msh;

    int b = blockIdx.x;
    int t = threadIdx.x;
    int lane = t & 31, warp = t >> 5;

    hist[t] = 0; hist[t + 1024] = 0;
    __syncthreads();

    unsigned long long k0 = g_key64[b * NN + t];
    unsigned long long k1 = g_key64[b * NN + t + 1024];
    bool v0 = (unsigned)(k0 >> 32) > 0x80000000u;
    bool v1 = (unsigned)(k1 >> 32) > 0x80000000u;
    int bk0 = (int)((k0 >> 44) & (NBK - 1));
    int bk1 = (int)((k1 >> 44) & (NBK - 1));
    if (v0) atomicAdd(&hist[bk0], 1);
    if (v1) atomicAdd(&hist[bk1], 1);
    __syncthreads();

    // exclusive scan over DESCENDING bucket order (largest key first)
    int c0 = hist[NBK - 1 - 2 * t];
    int c1 = hist[NBK - 2 - 2 * t];
    int sum = c0 + c1;
    int inc = sum;
    #pragma unroll
    for (int o = 1; o < 32; o <<= 1) {
        int a = __shfl_up_sync(0xFFFFFFFFu, inc, o);
        if (lane >= o) inc += a;
    }
    if (lane == 31) wsum[warp] = inc;
    __syncthreads();
    if (warp == 0) {
        int wv = wsum[lane];
        int winc = wv;
        #pragma unroll
        for (int o = 1; o < 32; o <<= 1) {
            int a = __shfl_up_sync(0xFFFFFFFFu, winc, o);
            if (lane >= o) winc += a;
        }
        wsum[lane] = winc - wv;   // exclusive warp offsets
    }
    __syncthreads();
    int excl = wsum[warp] + (inc - sum);
    offs[NBK - 1 - 2 * t] = excl;
    offs[NBK - 2 - 2 * t] = excl + c0;
    if (t == 1023) Msh = excl + sum;   // total valid count
    __syncthreads();

    // cursors = offs, then scatter keys into bucket slots
    hist[t] = offs[t];
    hist[t + 1024] = offs[t + 1024];
    __syncthreads();
    if (v0) { int s = atomicAdd(&hist[bk0], 1); skey[s] = k0; }
    if (v1) { int s = atomicAdd(&hist[bk1], 1); skey[s] = k1; }
    __syncthreads();

    // per-bucket insertion sort, descending u64 (stability via idx in low bits)
    #pragma unroll
    for (int rr = 0; rr < 2; rr++) {
        int bk = t + rr * 1024;
        int s = offs[bk], e = hist[bk];
        for (int i = s + 1; i < e; i++) {
            unsigned long long key = skey[i];
            int j = i - 1;
            while (j >= s && skey[j] < key) { skey[j + 1] = skey[j]; j--; }
            skey[j + 1] = key;
        }
    }
    __syncthreads();

    // gather sorted attributes to global
    int M = Msh;
    #pragma unroll
    for (int rr = 0; rr < 2; rr++) {
        int p = t + rr * 1024;
        if (p < M) {
            unsigned n = 0xFFFFFFFFu - (unsigned)(skey[p] & 0xFFFFFFFFu);
            int g = b * NN + (int)n;
            int d = b * NN + p;
            g_xyxy_s[d] = g_xyxy[g];
            g_obj_s [d] = g_obj [g];
            g_conf_s[d] = g_conf[g];
            g_cls_s [d] = (unsigned char)g_cls[g];
        }
    }
    if (t == 0) g_M[b] = M;
}

// ---------------- kernel 3: per-(batch,class) greedy NMS + output --------
#define NMS_WARPS 4
#define LCAP 128
__global__ __launch_bounds__(NMS_WARPS * 32) void nms_kernel(float* __restrict__ out)
{
    __shared__ unsigned short list_s [NMS_WARPS][LCAP];
    __shared__ unsigned char  alive_s[NMS_WARPS][LCAP];

    int warp = threadIdx.x >> 5;
    int lane = threadIdx.x & 31;
    int w = blockIdx.x * NMS_WARPS + warp;
    if (w >= BB * CC) return;
    int b = w / CC;
    int c = w % CC;

    int M = g_M[b];
    const unsigned char* cls = g_cls_s + b * NN;
    unsigned short* list  = list_s [warp];
    unsigned char*  alive = alive_s[warp];

    // ordered ballot-compaction of class members within the valid prefix
    int K = 0;
    for (int base = 0; base < M; base += 32) {
        int p = base + lane;
        bool match = (p < M) && (cls[p] == (unsigned char)c);
        unsigned mask = __ballot_sync(0xFFFFFFFFu, match);
        if (match) {
            int d = K + __popc(mask & ((1u << lane) - 1u));
            if (d < LCAP) list[d] = (unsigned short)p;
        }
        K += __popc(mask);
    }
    if (K > LCAP) K = LCAP;
    for (int k2 = lane; k2 < K; k2 += 32) alive[k2] = 1;
    __syncwarp();

    const float4* boxes = g_xyxy_s + b * NN;

    for (int i = 0; i < K - 1; i++) {
        if (alive[i]) {
            float4 bi = boxes[list[i]];
            float areaI = (bi.z - bi.x + 1.0f) * (bi.w - bi.y + 1.0f);
            for (int j = i + 1 + lane; j < K; j += 32) {
                if (alive[j]) {
                    float4 bj = boxes[list[j]];
                    float x1 = fmaxf(bi.x, bj.x);
                    float y1 = fmaxf(bi.y, bj.y);
                    float x2 = fminf(bi.z, bj.z);
                    float y2 = fminf(bi.w, bj.w);
                    float iw = fmaxf(x2 - x1 + 1.0f, 0.0f);
                    float ih = fmaxf(y2 - y1 + 1.0f, 0.0f);
                    float inter = iw * ih;
                    float areaJ = (bj.z - bj.x + 1.0f) * (bj.w - bj.y + 1.0f);
                    float iou = inter / (areaI + areaJ - inter);
                    if (iou >= 0.5f) alive[j] = 0;
                }
            }
        }
        __syncwarp();
    }

    for (int k2 = lane; k2 < K; k2 += 32) {
        if (alive[k2]) {
            int p = list[k2];
            float4 bx = boxes[p];
            float4* row = (float4*)(out + ((size_t)(b * NN + p)) * 8);
            row[0] = make_float4((float)b, bx.x, bx.y, bx.z);
            row[1] = make_float4(bx.w, g_obj_s[b * NN + p],
                                 g_conf_s[b * NN + p], (float)c);
        }
    }
}

// ---------------- launch ---------------------------------------------------
extern "C" void kernel_launch(void* const* d_in, const int* in_sizes, int n_in,
                              void* d_out, int out_size)
{
    const float* boxes  = nullptr;
    const float* objn   = nullptr;
    const float* logits = nullptr;
    for (int i = 0; i < n_in; i++) {
        if      (in_sizes[i] == BB * NN * 4)  boxes  = (const float*)d_in[i];
        else if (in_sizes[i] == BB * NN)      objn   = (const float*)d_in[i];
        else if (in_sizes[i] == BB * NN * CC) logits = (const float*)d_in[i];
    }
    float* out = (float*)d_out;

    prep_kernel<<<(BB * NN + 127) / 128, 128>>>(boxes, objn, logits, out);
    rank_kernel<<<BB, 1024>>>();
    nms_kernel<<<(BB * CC + NMS_WARPS - 1) / NMS_WARPS, NMS_WARPS * 32>>>(out);
}

// round 8
// speedup vs baseline: 1.8163x; 1.2551x over previous
#include <cuda_runtime.h>
#include <cstdint>
#include <float.h>

#define BB 16
#define NN 2048
#define CC 80
#define NBK 2048          // key buckets (mantissa bits [22:12])

// ---------------- scratch (device globals; no allocations) ----------------
__device__ float4             g_xyxy [BB * NN];
__device__ float              g_obj  [BB * NN];
__device__ float              g_conf [BB * NN];
__device__ int                g_cls  [BB * NN];
__device__ unsigned long long g_key64[BB * NN];

__device__ float4             g_xyxy_s[BB * NN];
__device__ float              g_obj_s [BB * NN];
__device__ float              g_conf_s[BB * NN];
__device__ unsigned char      g_cls_s [BB * NN];
__device__ int                g_M[BB];

// ---------------- kernel 1: prep, 4 threads/element, valid-gated ----------
__global__ __launch_bounds__(128) void prep_kernel(const float* __restrict__ boxes,
                                                   const float* __restrict__ objn,
                                                   const float* __restrict__ logits,
                                                   float* __restrict__ out)
{
    int gid = blockIdx.x * blockDim.x + threadIdx.x;
    int gw  = gid >> 2;             // element index
    int sub = gid & 3;              // 0..3 within element group
    if (gw >= BB * NN) return;

    float ob = objn[gw];            // broadcast-coalesced within group
    bool valid = ob > 0.5f;

    if (sub == 0) {
        // sort key always (invalid -> -1.0 sorts to the back)
        unsigned u = __float_as_uint(valid ? ob : -1.0f);
        u = (u & 0x80000000u) ? ~u : (u | 0x80000000u);
        unsigned idx = (unsigned)(gw & (NN - 1));
        g_key64[gw] = ((unsigned long long)u << 32) | (0xFFFFFFFFu - idx);
        // output row halves split across sub 0/1
        int b = gw >> 11;
        ((float4*)(out + (size_t)gw * 8))[0] = make_float4((float)b, 0.f, 0.f, 0.f);
    } else if (sub == 1) {
        ((float4*)(out + (size_t)gw * 8))[1] = make_float4(0.f, 0.f, 0.f, 0.f);
    }

    if (!valid) return;             // invalid: downstream never reads attrs

    // each sub-thread scans 20 logits (5 float4)
    const float4* lg4 = (const float4*)(logits + (size_t)gw * CC) + sub * 5;
    float v = -FLT_MAX;
    int   vi = 0;
    #pragma unroll
    for (int q = 0; q < 5; q++) {
        float4 x = lg4[q];
        int k = sub * 20 + q * 4;
        if (x.x > v) { v = x.x; vi = k;     }
        if (x.y > v) { v = x.y; vi = k + 1; }
        if (x.z > v) { v = x.z; vi = k + 2; }
        if (x.w > v) { v = x.w; vi = k + 3; }
    }
    // reduce across the 4-lane group, tie -> lowest class index
    #pragma unroll
    for (int o = 1; o <= 2; o <<= 1) {
        float v2 = __shfl_xor_sync(0xFFFFFFFFu, v, o);
        int   i2 = __shfl_xor_sync(0xFFFFFFFFu, vi, o);
        if (v2 > v || (v2 == v && i2 < vi)) { v = v2; vi = i2; }
    }

    if (sub == 0) {
        float4 bx = ((const float4*)boxes)[gw];
        float4 xy;
        xy.x = bx.x - bx.z * 0.5f;
        xy.y = bx.y - bx.w * 0.5f;
        xy.z = bx.x + bx.z * 0.5f;
        xy.w = bx.y + bx.w * 0.5f;
        g_xyxy[gw] = xy;
        g_obj [gw] = ob;
        g_conf[gw] = v;
        g_cls [gw] = vi;
    }
}

// ---------------- kernel 2: per-batch counting sort of valid elements ----
__global__ __launch_bounds__(1024) void rank_kernel()
{
    __shared__ int                hist[NBK];
    __shared__ int                offs[NBK];
    __shared__ unsigned long long skey[NN];
    __shared__ int                wsum[32];
    __shared__ int                Msh;

    int b = blockIdx.x;
    int t = threadIdx.x;
    int lane = t & 31, warp = t >> 5;

    hist[t] = 0; hist[t + 1024] = 0;
    __syncthreads();

    unsigned long long k0 = g_key64[b * NN + t];
    unsigned long long k1 = g_key64[b * NN + t + 1024];
    bool v0 = (unsigned)(k0 >> 32) > 0x80000000u;
    bool v1 = (unsigned)(k1 >> 32) > 0x80000000u;
    int bk0 = (int)((k0 >> 44) & (NBK - 1));
    int bk1 = (int)((k1 >> 44) & (NBK - 1));
    if (v0) atomicAdd(&hist[bk0], 1);
    if (v1) atomicAdd(&hist[bk1], 1);
    __syncthreads();

    int c0 = hist[NBK - 1 - 2 * t];
    int c1 = hist[NBK - 2 - 2 * t];
    int sum = c0 + c1;
    int inc = sum;
    #pragma unroll
    for (int o = 1; o < 32; o <<= 1) {
        int a = __shfl_up_sync(0xFFFFFFFFu, inc, o);
        if (lane >= o) inc += a;
    }
    if (lane == 31) wsum[warp] = inc;
    __syncthreads();
    if (warp == 0) {
        int wv = wsum[lane];
        int winc = wv;
        #pragma unroll
        for (int o = 1; o < 32; o <<= 1) {
            int a = __shfl_up_sync(0xFFFFFFFFu, winc, o);
            if (lane >= o) winc += a;
        }
        wsum[lane] = winc - wv;
    }
    __syncthreads();
    int excl = wsum[warp] + (inc - sum);
    offs[NBK - 1 - 2 * t] = excl;
    offs[NBK - 2 - 2 * t] = excl + c0;
    if (t == 1023) Msh = excl + sum;
    __syncthreads();

    hist[t] = offs[t];
    hist[t + 1024] = offs[t + 1024];
    __syncthreads();
    if (v0) { int s = atomicAdd(&hist[bk0], 1); skey[s] = k0; }
    if (v1) { int s = atomicAdd(&hist[bk1], 1); skey[s] = k1; }
    __syncthreads();

    #pragma unroll
    for (int rr = 0; rr < 2; rr++) {
        int bk = t + rr * 1024;
        int s = offs[bk], e = hist[bk];
        for (int i = s + 1; i < e; i++) {
            unsigned long long key = skey[i];
            int j = i - 1;
            while (j >= s && skey[j] < key) { skey[j + 1] = skey[j]; j--; }
            skey[j + 1] = key;
        }
    }
    __syncthreads();

    int M = Msh;
    #pragma unroll
    for (int rr = 0; rr < 2; rr++) {
        int p = t + rr * 1024;
        if (p < M) {
            unsigned n = 0xFFFFFFFFu - (unsigned)(skey[p] & 0xFFFFFFFFu);
            int g = b * NN + (int)n;
            int d = b * NN + p;
            g_xyxy_s[d] = g_xyxy[g];
            g_obj_s [d] = g_obj [g];
            g_conf_s[d] = g_conf[g];
            g_cls_s [d] = (unsigned char)g_cls[g];
        }
    }
    if (t == 0) g_M[b] = M;
}

// ---------------- kernel 3: NMS, block per (batch, 8-class group) ---------
// block stages cls + boxes of the valid prefix into smem, then 8 warps each
// run one class's compaction + greedy NMS entirely from smem.
#define NMS_CW 8           // classes (=warps) per block
#define NMS_GRP (CC / NMS_CW)   // 10 groups per batch
#define LCAP 128
__global__ __launch_bounds__(NMS_CW * 32) void nms_kernel(float* __restrict__ out)
{
    __shared__ float4        sbox[NN];            // 32 KB
    __shared__ unsigned char scls[NN];            // 2 KB
    __shared__ unsigned short list_s [NMS_CW][LCAP];
    __shared__ unsigned char  alive_s[NMS_CW][LCAP];

    int warp = threadIdx.x >> 5;
    int lane = threadIdx.x & 31;
    int b    = blockIdx.x / NMS_GRP;
    int grp  = blockIdx.x % NMS_GRP;
    int c    = grp * NMS_CW + warp;

    int M = g_M[b];

    // cooperative stage of the valid prefix
    for (int p = threadIdx.x; p < M; p += NMS_CW * 32) {
        sbox[p] = g_xyxy_s[b * NN + p];
        scls[p] = g_cls_s [b * NN + p];
    }
    __syncthreads();

    unsigned short* list  = list_s [warp];
    unsigned char*  alive = alive_s[warp];

    // ordered ballot-compaction of class members (from smem)
    int K = 0;
    for (int base = 0; base < M; base += 32) {
        int p = base + lane;
        bool match = (p < M) && (scls[p] == (unsigned char)c);
        unsigned mask = __ballot_sync(0xFFFFFFFFu, match);
        if (match) {
            int d = K + __popc(mask & ((1u << lane) - 1u));
            if (d < LCAP) list[d] = (unsigned short)p;
        }
        K += __popc(mask);
    }
    if (K > LCAP) K = LCAP;
    for (int k2 = lane; k2 < K; k2 += 32) alive[k2] = 1;
    __syncwarp();

    // greedy NMS from smem boxes
    for (int i = 0; i < K - 1; i++) {
        if (alive[i]) {
            float4 bi = sbox[list[i]];
            float areaI = (bi.z - bi.x + 1.0f) * (bi.w - bi.y + 1.0f);
            for (int j = i + 1 + lane; j < K; j += 32) {
                if (alive[j]) {
                    float4 bj = sbox[list[j]];
                    float x1 = fmaxf(bi.x, bj.x);
                    float y1 = fmaxf(bi.y, bj.y);
                    float x2 = fminf(bi.z, bj.z);
                    float y2 = fminf(bi.w, bj.w);
                    float iw = fmaxf(x2 - x1 + 1.0f, 0.0f);
                    float ih = fmaxf(y2 - y1 + 1.0f, 0.0f);
                    float inter = iw * ih;
                    float areaJ = (bj.z - bj.x + 1.0f) * (bj.w - bj.y + 1.0f);
                    float iou = inter / (areaI + areaJ - inter);
                    if (iou >= 0.5f) alive[j] = 0;
                }
            }
        }
        __syncwarp();
    }

    // write kept detections
    for (int k2 = lane; k2 < K; k2 += 32) {
        if (alive[k2]) {
            int p = list[k2];
            float4 bx = sbox[p];
            float4* row = (float4*)(out + ((size_t)(b * NN + p)) * 8);
            row[0] = make_float4((float)b, bx.x, bx.y, bx.z);
            row[1] = make_float4(bx.w, g_obj_s[b * NN + p],
                                 g_conf_s[b * NN + p], (float)c);
        }
    }
}

// ---------------- launch ---------------------------------------------------
extern "C" void kernel_launch(void* const* d_in, const int* in_sizes, int n_in,
                              void* d_out, int out_size)
{
    const float* boxes  = nullptr;
    const float* objn   = nullptr;
    const float* logits = nullptr;
    for (int i = 0; i < n_in; i++) {
        if      (in_sizes[i] == BB * NN * 4)  boxes  = (const float*)d_in[i];
        else if (in_sizes[i] == BB * NN)      objn   = (const float*)d_in[i];
        else if (in_sizes[i] == BB * NN * CC) logits = (const float*)d_in[i];
    }
    float* out = (float*)d_out;

    prep_kernel<<<(BB * NN * 4 + 127) / 128, 128>>>(boxes, objn, logits, out);
    rank_kernel<<<BB, 1024>>>();
    nms_kernel<<<BB * NMS_GRP, NMS_CW * 32>>>(out);
}